// round 13
// baseline (speedup 1.0000x reference)
#include <cuda_runtime.h>
#include <cstdint>

#define H 128
#define W 128
#define NS 8
#define TY 32
#define SROWS (TY + 8)    // 40
#define SCOLS 136         // x_pad[c] = x[c-4], c in [0,136)
#define EC    (SCOLS / 2) // 68 entries per parity row
#define SSPLIT 2          // s-groups per block = NS/SSPLIT = 4

typedef unsigned long long u64;

__device__ __forceinline__ void fma2(u64& acc, u64 a, u64 b) {
    asm("fma.rn.f32x2 %0, %1, %2, %0;" : "+l"(acc) : "l"(a), "l"(b));
}
__device__ __forceinline__ void mul2(u64& d, u64 a, u64 b) {
    asm("mul.rn.f32x2 %0, %1, %2;" : "=l"(d) : "l"(a), "l"(b));
}
__device__ __forceinline__ void unpk(u64 v, float& lo, float& hi) {
    asm("mov.b64 {%0, %1}, %2;" : "=f"(lo), "=f"(hi) : "l"(v));
}

__global__ void __launch_bounds__(128)
shifted_conv_kernel(const float* __restrict__ tens,
                    const float* __restrict__ filters,
                    const int* __restrict__ shifts,
                    float* __restrict__ out)
{
    // Parity-deinterleaved tile, two copies per parity shifted by one entry:
    //   s_p[p][0][r][i] = x_pad[r][2i+p]
    //   s_p[p][1][r][i] = x_pad[r][2i+p+2]
    __shared__ __align__(16) float s_p[2][2][SROWS][EC];   // 43.5 KB
    __shared__ __align__(16) float2 s_fp[NS][25];          // splatted (f,f)
    __shared__ int s_sh[NS * 2];

    const int n     = blockIdx.x;
    const int y0    = blockIdx.y * TY;        // 0,32,64,96
    const int sbase = blockIdx.z * (NS / SSPLIT);  // 0 or 4
    const int tid   = threadIdx.x;
    const int lane  = tid & 31;
    const int wrp   = tid >> 5;

    for (int i = tid; i < NS * 25; i += 128) {
        float f = filters[i];
        s_fp[i / 25][i % 25] = make_float2(f, f);
    }
    if (tid < NS * 2) s_sh[tid] = shifts[tid];

    const float* inp = tens + (size_t)n * (H * W);
    for (int idx = tid; idx < SROWS * SCOLS; idx += 128) {
        int r  = idx / SCOLS;
        int c  = idx - r * SCOLS;
        int gy = y0 - 4 + r;
        int gx = c - 4;
        float v = 0.0f;
        if (gy >= 0 && gy < H && gx >= 0 && gx < W)
            v = inp[gy * W + gx];
        int p = c & 1, i = c >> 1;
        s_p[p][0][r][i] = v;
        if (i > 0) s_p[p][1][r][i - 1] = v;
    }
    for (int r = tid; r < SROWS; r += 128) {   // copy1 tails: x_pad[136/137]=0
        s_p[0][1][r][EC - 1] = 0.0f;
        s_p[1][1][r][EC - 1] = 0.0f;
    }
    __syncthreads();

    const int ybase = wrp * 8;          // 8 output rows per warp (rotation)
    const int xo    = 4 * lane;         // 4 output cols per lane
    float* outw = out + (size_t)n * (NS * H * W)
                      + (size_t)(y0 + ybase) * W + xo;

    #pragma unroll 1
    for (int s = sbase; s < sbase + NS / SSPLIT; ++s) {
        const int sy = s_sh[2 * s + 0];
        const int sx = s_sh[2 * s + 1];

        // Filter splat pairs: 25 aligned LDS.64, zero MOVs, reused for 8 rows.
        u64 fp[25];
        #pragma unroll
        for (int t = 0; t < 25; ++t) {
            float2 v = s_fp[s][t];
            fp[t] = reinterpret_cast<u64&>(v);
        }

        const int rowbase = ybase + 4 - sy;   // [0, 28]
        const int a       = 4 - sx;           // [0, 4]
        // Pair t = (x_pad[c0+t], x_pad[c0+t+2]), c0 = xo + a. Same-parity
        // adjacent entries; copy index selects 8B alignment. (Verified R11/12.)
        const float* bp[6];
        #pragma unroll
        for (int t = 0; t < 6; ++t) {
            int p = (a + t) & 1;
            int h = (a + t - p) >> 1;
            bp[t] = &s_p[p][h & 1][rowbase][2 * lane + (h & ~1)];
        }

        float* ops = outw + (size_t)s * (H * W);

        // Sliding-window over 12 input rows; output row y live for k in
        // [y, y+4]; store right after its last tap -> <=5 acc rows live.
        u64 acc[8][2];
        #pragma unroll
        for (int k = 0; k < 12; ++k) {
            u64 q[6];
            #pragma unroll
            for (int t = 0; t < 6; ++t) {
                float2 v = *(const float2*)(bp[t] + k * EC);  // aligned LDS.64
                q[t] = reinterpret_cast<u64&>(v);
            }
            #pragma unroll
            for (int y = 0; y < 8; ++y) {
                const int i = k - y;           // compile-time after unroll
                if (i == 0) {
                    mul2(acc[y][0], fp[0], q[0]);
                    mul2(acc[y][1], fp[0], q[1]);
                    #pragma unroll
                    for (int j = 1; j < 5; ++j) {
                        fma2(acc[y][0], fp[j], q[j]);
                        fma2(acc[y][1], fp[j], q[j + 1]);
                    }
                } else if (i >= 1 && i < 5) {
                    #pragma unroll
                    for (int j = 0; j < 5; ++j) {
                        fma2(acc[y][0], fp[i * 5 + j], q[j]);
                        fma2(acc[y][1], fp[i * 5 + j], q[j + 1]);
                    }
                }
            }
            const int yd = k - 4;
            if (yd >= 0 && yd < 8) {
                float o0, o2, o1, o3;
                unpk(acc[yd][0], o0, o2);
                unpk(acc[yd][1], o1, o3);
                *(float4*)(ops + yd * W) = make_float4(o0, o1, o2, o3);
            }
        }
    }
}

extern "C" void kernel_launch(void* const* d_in, const int* in_sizes, int n_in,
                              void* d_out, int out_size)
{
    const float* tens    = (const float*)d_in[0];
    const float* filters = (const float*)d_in[1];
    const int*   shifts  = (const int*)d_in[2];
    float*       out     = (float*)d_out;

    dim3 grid(256, H / TY, SSPLIT);   // 2048 blocks: finer wave granularity
    shifted_conv_kernel<<<grid, 128>>>(tens, filters, shifts, out);
}